// round 1
// baseline (speedup 1.0000x reference)
#include <cuda_runtime.h>

#define B   32
#define CIN 256
#define COUT 256
#define FD  64
#define TD  64
#define KEXP 4
#define TEMP 30.0f

// Static device scratch (allowed; no runtime allocation).
__device__ float g_att[B * KEXP];
__device__ float g_agg[(size_t)B * COUT * CIN * 9];   // 18,874,368 floats = 75.5 MB

// ---------------------------------------------------------------------------
// Kernel 1: attention = softmax((g @ dense_w + dense_b) / TEMP)  -> g_att[b,k]
// One block, 128 threads: thread = (b, k).
// ---------------------------------------------------------------------------
__global__ void attn_kernel(const float* __restrict__ g,
                            const float* __restrict__ dw,
                            const float* __restrict__ db) {
    int t = threadIdx.x;            // 0..127
    int b = t >> 2;
    int k = t & 3;
    const float* gb = g + b * 256;
    float s = 0.f;
#pragma unroll 4
    for (int c = 0; c < 256; ++c)
        s += gb[c] * dw[c * 4 + k];
    s = (s + db[k]) * (1.0f / TEMP);

    // softmax over groups of 4 lanes (groups are lane-aligned)
    float m = s;
    m = fmaxf(m, __shfl_xor_sync(0xffffffffu, m, 1));
    m = fmaxf(m, __shfl_xor_sync(0xffffffffu, m, 2));
    float e = expf(s - m);
    float sum = e;
    sum += __shfl_xor_sync(0xffffffffu, sum, 1);
    sum += __shfl_xor_sync(0xffffffffu, sum, 2);
    g_att[b * 4 + k] = e / sum;
}

// ---------------------------------------------------------------------------
// Kernel 2: g_agg[b, co, ci, kh, kw] = sum_k att[b,k] * W[k, co, ci, kh, kw]
// float4 over the contiguous (co,ci,kh,kw) index. Fully coalesced.
// ---------------------------------------------------------------------------
__global__ void agg_kernel(const float4* __restrict__ w) {
    const int PER_B4 = COUT * CIN * 9 / 4;   // 147456
    int i = blockIdx.x * blockDim.x + threadIdx.x;
    if (i >= B * PER_B4) return;
    int b = i / PER_B4;
    int r = i - b * PER_B4;
    float a0 = g_att[b * 4 + 0];
    float a1 = g_att[b * 4 + 1];
    float a2 = g_att[b * 4 + 2];
    float a3 = g_att[b * 4 + 3];
    float4 w0 = w[r];
    float4 w1 = w[PER_B4 + r];
    float4 w2 = w[2 * PER_B4 + r];
    float4 w3 = w[3 * PER_B4 + r];
    float4 o;
    o.x = a0 * w0.x + a1 * w1.x + a2 * w2.x + a3 * w3.x;
    o.y = a0 * w0.y + a1 * w1.y + a2 * w2.y + a3 * w3.y;
    o.z = a0 * w0.z + a1 * w1.z + a2 * w2.z + a3 * w3.z;
    o.w = a0 * w0.w + a1 * w1.w + a2 * w2.w + a3 * w3.w;
    reinterpret_cast<float4*>(g_agg)[i] = o;
}

// ---------------------------------------------------------------------------
// Kernel 3: per-sample 3x3 conv (pad 1, stride 1), direct, fp32.
// Block = (batch b, 64 output channels, 2 output rows x 64 cols).
// 256 threads: tco = tid>>4 (16 groups of 4 co), tpx = tid&15 (16 groups of
// 8 contiguous pixels). Per-thread register tile: 4 co x 8 px.
// c_in consumed in chunks of 8 through shared memory.
// ---------------------------------------------------------------------------
#define CI_CHUNK 8

__global__ __launch_bounds__(256, 2)
void conv_kernel(const float* __restrict__ x, float* __restrict__ out) {
    __shared__ float xs[CI_CHUNK][4][66];        // [ci][frow (f0-1..f0+2)][col+1]
    __shared__ float ws[CI_CHUNK * 9][64];       // [(ci*9 + kh*3 + kw)][co_local]

    const int b       = blockIdx.z;
    const int co_base = blockIdx.y * 64;
    const int f0      = blockIdx.x * 2;

    const int tid  = threadIdx.x;
    const int tco  = tid >> 4;          // 0..15
    const int tpx  = tid & 15;          // 0..15
    const int r    = tpx >> 3;          // row within 2-row tile
    const int col0 = (tpx & 7) * 8;     // first of 8 contiguous output cols
    const int fo   = f0 + r;

    const float* xb = x + (size_t)b * CIN * FD * TD;
    const float* ab = g_agg + ((size_t)b * COUT + co_base) * (CIN * 9);

    float acc[4][8];
#pragma unroll
    for (int cc = 0; cc < 4; ++cc)
#pragma unroll
        for (int p = 0; p < 8; ++p) acc[cc][p] = 0.f;

    for (int ci0 = 0; ci0 < CIN; ci0 += CI_CHUNK) {
        // --- load x tile (with padding) ---
        for (int i = tid; i < CI_CHUNK * 4 * 66; i += 256) {
            int ci  = i / 264;
            int rem = i - ci * 264;
            int rr  = rem / 66;
            int c   = rem - rr * 66;
            int inf = f0 - 1 + rr;
            int int_ = c - 1;
            float v = 0.f;
            if ((unsigned)inf < (unsigned)FD && (unsigned)int_ < (unsigned)TD)
                v = xb[((ci0 + ci) * FD + inf) * TD + int_];
            xs[ci][rr][c] = v;
        }
        // --- load weight tile: contiguous 72-float runs per co ---
        for (int i = tid; i < CI_CHUNK * 9 * 64; i += 256) {
            int col = i / 72;               // co_local
            int j   = i - col * 72;         // ci*9 + kk
            ws[j][col] = ab[(size_t)col * (CIN * 9) + ci0 * 9 + j];
        }
        __syncthreads();

#pragma unroll
        for (int ci = 0; ci < CI_CHUNK; ++ci) {
#pragma unroll
            for (int kh = 0; kh < 3; ++kh) {
                float xv[10];
#pragma unroll
                for (int j = 0; j < 10; ++j)
                    xv[j] = xs[ci][r + kh][col0 + j];
#pragma unroll
                for (int kw = 0; kw < 3; ++kw) {
                    const float4 w4 =
                        *reinterpret_cast<const float4*>(&ws[ci * 9 + kh * 3 + kw][tco * 4]);
                    float wv[4] = {w4.x, w4.y, w4.z, w4.w};
#pragma unroll
                    for (int cc = 0; cc < 4; ++cc)
#pragma unroll
                        for (int p = 0; p < 8; ++p)
                            acc[cc][p] += wv[cc] * xv[p + kw];
                }
            }
        }
        __syncthreads();
    }

    // --- epilogue: 4 co x 8 px, two float4 stores per co ---
#pragma unroll
    for (int cc = 0; cc < 4; ++cc) {
        size_t o = (((size_t)b * COUT + co_base + tco * 4 + cc) * FD + fo) * TD + col0;
        float4 v0 = make_float4(acc[cc][0], acc[cc][1], acc[cc][2], acc[cc][3]);
        float4 v1 = make_float4(acc[cc][4], acc[cc][5], acc[cc][6], acc[cc][7]);
        *reinterpret_cast<float4*>(&out[o])     = v0;
        *reinterpret_cast<float4*>(&out[o + 4]) = v1;
    }
}

// ---------------------------------------------------------------------------
extern "C" void kernel_launch(void* const* d_in, const int* in_sizes, int n_in,
                              void* d_out, int out_size) {
    const float* x   = (const float*)d_in[0];   // (32,256,64,64)
    const float* g   = (const float*)d_in[1];   // (32,256)
    const float* w   = (const float*)d_in[2];   // (4,256,256,3,3)
    const float* dw  = (const float*)d_in[3];   // (256,4)
    const float* db  = (const float*)d_in[4];   // (4,)
    float* out = (float*)d_out;

    attn_kernel<<<1, 128>>>(g, dw, db);

    const int PER_B4 = COUT * CIN * 9 / 4;
    int total4 = B * PER_B4;                    // 4,718,592
    agg_kernel<<<(total4 + 255) / 256, 256>>>((const float4*)w);

    dim3 grid(FD / 2, COUT / 64, B);            // (32, 4, 32)
    conv_kernel<<<grid, 256>>>(x, out);
}

// round 2
// speedup vs baseline: 1.0016x; 1.0016x over previous
#include <cuda_runtime.h>

#define B   32
#define CIN 256
#define COUT 256
#define FD  64
#define TD  64
#define KEXP 4
#define TEMP 30.0f

// Static device scratch (allowed; no runtime allocation).
__device__ float g_att[B * KEXP];
__device__ float g_agg[(size_t)B * COUT * CIN * 9];   // 18,874,368 floats = 75.5 MB

// ---------------------------------------------------------------------------
// Kernel 1: attention = softmax((g @ dense_w + dense_b) / TEMP)  -> g_att[b,k]
// One block, 128 threads: thread = (b, k).
// ---------------------------------------------------------------------------
__global__ void attn_kernel(const float* __restrict__ g,
                            const float* __restrict__ dw,
                            const float* __restrict__ db) {
    int t = threadIdx.x;            // 0..127
    int b = t >> 2;
    int k = t & 3;
    const float* gb = g + b * 256;
    float s = 0.f;
#pragma unroll 4
    for (int c = 0; c < 256; ++c)
        s += gb[c] * dw[c * 4 + k];
    s = (s + db[k]) * (1.0f / TEMP);

    // softmax over groups of 4 lanes (groups are lane-aligned)
    float m = s;
    m = fmaxf(m, __shfl_xor_sync(0xffffffffu, m, 1));
    m = fmaxf(m, __shfl_xor_sync(0xffffffffu, m, 2));
    float e = expf(s - m);
    float sum = e;
    sum += __shfl_xor_sync(0xffffffffu, sum, 1);
    sum += __shfl_xor_sync(0xffffffffu, sum, 2);
    g_att[b * 4 + k] = e / sum;
}

// ---------------------------------------------------------------------------
// Kernel 2: g_agg[b, co, ci, kh, kw] = sum_k att[b,k] * W[k, co, ci, kh, kw]
// float4 over the contiguous (co,ci,kh,kw) index. Fully coalesced.
// ---------------------------------------------------------------------------
__global__ void agg_kernel(const float4* __restrict__ w) {
    const int PER_B4 = COUT * CIN * 9 / 4;   // 147456
    int i = blockIdx.x * blockDim.x + threadIdx.x;
    if (i >= B * PER_B4) return;
    int b = i / PER_B4;
    int r = i - b * PER_B4;
    float a0 = g_att[b * 4 + 0];
    float a1 = g_att[b * 4 + 1];
    float a2 = g_att[b * 4 + 2];
    float a3 = g_att[b * 4 + 3];
    float4 w0 = w[r];
    float4 w1 = w[PER_B4 + r];
    float4 w2 = w[2 * PER_B4 + r];
    float4 w3 = w[3 * PER_B4 + r];
    float4 o;
    o.x = a0 * w0.x + a1 * w1.x + a2 * w2.x + a3 * w3.x;
    o.y = a0 * w0.y + a1 * w1.y + a2 * w2.y + a3 * w3.y;
    o.z = a0 * w0.z + a1 * w1.z + a2 * w2.z + a3 * w3.z;
    o.w = a0 * w0.w + a1 * w1.w + a2 * w2.w + a3 * w3.w;
    reinterpret_cast<float4*>(g_agg)[i] = o;
}

// ---------------------------------------------------------------------------
// Kernel 3: per-sample 3x3 conv (pad 1, stride 1), direct, fp32.
// Block = (batch b, 64 output channels, 2 output rows x 64 cols).
// 256 threads: tco = tid>>4 (16 groups of 4 co), tpx = tid&15 (16 groups of
// 8 contiguous pixels). Per-thread register tile: 4 co x 8 px.
// c_in consumed in chunks of 8 through shared memory.
// ---------------------------------------------------------------------------
#define CI_CHUNK 8

__global__ __launch_bounds__(256, 2)
void conv_kernel(const float* __restrict__ x, float* __restrict__ out) {
    __shared__ float xs[CI_CHUNK][4][66];        // [ci][frow (f0-1..f0+2)][col+1]
    __shared__ float ws[CI_CHUNK * 9][64];       // [(ci*9 + kh*3 + kw)][co_local]

    const int b       = blockIdx.z;
    const int co_base = blockIdx.y * 64;
    const int f0      = blockIdx.x * 2;

    const int tid  = threadIdx.x;
    const int tco  = tid >> 4;          // 0..15
    const int tpx  = tid & 15;          // 0..15
    const int r    = tpx >> 3;          // row within 2-row tile
    const int col0 = (tpx & 7) * 8;     // first of 8 contiguous output cols
    const int fo   = f0 + r;

    const float* xb = x + (size_t)b * CIN * FD * TD;
    const float* ab = g_agg + ((size_t)b * COUT + co_base) * (CIN * 9);

    float acc[4][8];
#pragma unroll
    for (int cc = 0; cc < 4; ++cc)
#pragma unroll
        for (int p = 0; p < 8; ++p) acc[cc][p] = 0.f;

    for (int ci0 = 0; ci0 < CIN; ci0 += CI_CHUNK) {
        // --- load x tile (with padding) ---
        for (int i = tid; i < CI_CHUNK * 4 * 66; i += 256) {
            int ci  = i / 264;
            int rem = i - ci * 264;
            int rr  = rem / 66;
            int c   = rem - rr * 66;
            int inf = f0 - 1 + rr;
            int int_ = c - 1;
            float v = 0.f;
            if ((unsigned)inf < (unsigned)FD && (unsigned)int_ < (unsigned)TD)
                v = xb[((ci0 + ci) * FD + inf) * TD + int_];
            xs[ci][rr][c] = v;
        }
        // --- load weight tile: contiguous 72-float runs per co ---
        for (int i = tid; i < CI_CHUNK * 9 * 64; i += 256) {
            int col = i / 72;               // co_local
            int j   = i - col * 72;         // ci*9 + kk
            ws[j][col] = ab[(size_t)col * (CIN * 9) + ci0 * 9 + j];
        }
        __syncthreads();

#pragma unroll
        for (int ci = 0; ci < CI_CHUNK; ++ci) {
#pragma unroll
            for (int kh = 0; kh < 3; ++kh) {
                float xv[10];
#pragma unroll
                for (int j = 0; j < 10; ++j)
                    xv[j] = xs[ci][r + kh][col0 + j];
#pragma unroll
                for (int kw = 0; kw < 3; ++kw) {
                    const float4 w4 =
                        *reinterpret_cast<const float4*>(&ws[ci * 9 + kh * 3 + kw][tco * 4]);
                    float wv[4] = {w4.x, w4.y, w4.z, w4.w};
#pragma unroll
                    for (int cc = 0; cc < 4; ++cc)
#pragma unroll
                        for (int p = 0; p < 8; ++p)
                            acc[cc][p] += wv[cc] * xv[p + kw];
                }
            }
        }
        __syncthreads();
    }

    // --- epilogue: 4 co x 8 px, two float4 stores per co ---
#pragma unroll
    for (int cc = 0; cc < 4; ++cc) {
        size_t o = (((size_t)b * COUT + co_base + tco * 4 + cc) * FD + fo) * TD + col0;
        float4 v0 = make_float4(acc[cc][0], acc[cc][1], acc[cc][2], acc[cc][3]);
        float4 v1 = make_float4(acc[cc][4], acc[cc][5], acc[cc][6], acc[cc][7]);
        *reinterpret_cast<float4*>(&out[o])     = v0;
        *reinterpret_cast<float4*>(&out[o + 4]) = v1;
    }
}

// ---------------------------------------------------------------------------
extern "C" void kernel_launch(void* const* d_in, const int* in_sizes, int n_in,
                              void* d_out, int out_size) {
    const float* x   = (const float*)d_in[0];   // (32,256,64,64)
    const float* g   = (const float*)d_in[1];   // (32,256)
    const float* w   = (const float*)d_in[2];   // (4,256,256,3,3)
    const float* dw  = (const float*)d_in[3];   // (256,4)
    const float* db  = (const float*)d_in[4];   // (4,)
    float* out = (float*)d_out;

    attn_kernel<<<1, 128>>>(g, dw, db);

    const int PER_B4 = COUT * CIN * 9 / 4;
    int total4 = B * PER_B4;                    // 4,718,592
    agg_kernel<<<(total4 + 255) / 256, 256>>>((const float4*)w);

    dim3 grid(FD / 2, COUT / 64, B);            // (32, 4, 32)
    conv_kernel<<<grid, 256>>>(x, out);
}

// round 5
// speedup vs baseline: 6.8105x; 6.7994x over previous
#include <cuda_runtime.h>
#include <cuda_fp16.h>
#include <cstdint>

#define TEMP 30.0f

// ---------------- static device scratch ----------------
__device__ float  g_att[32 * 4];
// aggregated fp16 weights: [b][coH(2)][chunk(16)][tap(9)][coL(128)][ci(16)]
__device__ __half g_w16[(size_t)32 * 2 * 16 * 9 * 128 * 16];
// transposed fp16 x: [b][f(64)][t(64)][ci(256)]
__device__ __half g_xT[(size_t)32 * 64 * 64 * 256];

// ---------------- helpers ----------------
__device__ __forceinline__ uint32_t smem_u32(const void* p) {
    uint32_t a;
    asm("{ .reg .u64 t; cvta.to.shared.u64 t, %1; cvt.u32.u64 %0, t; }" : "=r"(a) : "l"(p));
    return a;
}
__device__ __forceinline__ void cp16(uint32_t saddr, const void* g) {
    asm volatile("cp.async.cg.shared.global [%0], [%1], 16;" :: "r"(saddr), "l"(g));
}
__device__ __forceinline__ void ldsm_x4(uint32_t addr, uint32_t* r) {
    asm volatile("ldmatrix.sync.aligned.m8n8.x4.shared.b16 {%0,%1,%2,%3}, [%4];"
                 : "=r"(r[0]), "=r"(r[1]), "=r"(r[2]), "=r"(r[3]) : "r"(addr));
}
__device__ __forceinline__ void mma16816(float* d, const uint32_t* a,
                                         const uint32_t* b) {
    asm volatile(
        "mma.sync.aligned.m16n8k16.row.col.f32.f16.f16.f32 "
        "{%0,%1,%2,%3}, {%4,%5,%6,%7}, {%8,%9}, {%0,%1,%2,%3};"
        : "+f"(d[0]), "+f"(d[1]), "+f"(d[2]), "+f"(d[3])
        : "r"(a[0]), "r"(a[1]), "r"(a[2]), "r"(a[3]), "r"(b[0]), "r"(b[1]));
}

// ---------------------------------------------------------------------------
// Kernel 1: attention softmax -> g_att
// ---------------------------------------------------------------------------
__global__ void attn_kernel(const float* __restrict__ g,
                            const float* __restrict__ dw,
                            const float* __restrict__ db) {
    __shared__ float sp[4][4];
    int b = blockIdx.x, tid = threadIdx.x;
    int k = tid & 3, w = tid >> 5, lane = tid & 31;
    const float* gb = g + b * 256;
    float s = 0.f;
    for (int c = tid >> 2; c < 256; c += 32) s += gb[c] * dw[c * 4 + k];
    s += __shfl_xor_sync(~0u, s, 4);
    s += __shfl_xor_sync(~0u, s, 8);
    s += __shfl_xor_sync(~0u, s, 16);
    if (lane < 4) sp[w][k] = s;
    __syncthreads();
    if (tid < 4) {
        float t = (sp[0][k] + sp[1][k] + sp[2][k] + sp[3][k] + db[k]) * (1.f / TEMP);
        float m = t;
        m = fmaxf(m, __shfl_xor_sync(0xF, m, 1));
        m = fmaxf(m, __shfl_xor_sync(0xF, m, 2));
        float e = expf(t - m);
        float su = e;
        su += __shfl_xor_sync(0xF, su, 1);
        su += __shfl_xor_sync(0xF, su, 2);
        g_att[b * 4 + k] = e / su;
    }
}

// ---------------------------------------------------------------------------
// Kernel 2: aggregate expert weights -> fp16 tiled layout
// thread = (b, co, ci8 block of 8 ci)
// ---------------------------------------------------------------------------
__global__ void agg16_kernel(const float* __restrict__ w) {
    int idx = blockIdx.x * 256 + threadIdx.x;      // 262144
    int ci8 = idx & 31;
    int co  = (idx >> 5) & 255;
    int b   = idx >> 13;
    float acc[72];
#pragma unroll
    for (int e = 0; e < 72; ++e) acc[e] = 0.f;
#pragma unroll
    for (int k = 0; k < 4; ++k) {
        float a = g_att[b * 4 + k];
        const float4* wp =
            (const float4*)(w + (((size_t)k * 256 + co) * 256 + ci8 * 8) * 9);
#pragma unroll
        for (int q = 0; q < 18; ++q) {
            float4 f = wp[q];
            acc[q * 4 + 0] += a * f.x;
            acc[q * 4 + 1] += a * f.y;
            acc[q * 4 + 2] += a * f.z;
            acc[q * 4 + 3] += a * f.w;
        }
    }
    int coH = co >> 7, coL = co & 127, ch = ci8 >> 1, half8 = ci8 & 1;
#pragma unroll
    for (int kk = 0; kk < 9; ++kk) {
        __half2 h[4];
#pragma unroll
        for (int p = 0; p < 4; ++p)
            h[p] = __halves2half2(__float2half_rn(acc[(2 * p) * 9 + kk]),
                                  __float2half_rn(acc[(2 * p + 1) * 9 + kk]));
        __half* dst = g_w16 +
            (((((size_t)b * 2 + coH) * 16 + ch) * 9 + kk) * 128 + coL) * 16 + half8 * 8;
        *(uint4*)dst = *(uint4*)h;
    }
}

// ---------------------------------------------------------------------------
// Kernel 3: x -> fp16 transposed [b][f][t][ci]
// ---------------------------------------------------------------------------
__global__ void xT_kernel(const float* __restrict__ x) {
    __shared__ __half s[64][272];                  // 272*2B row = 16B aligned
    int f = blockIdx.x, b = blockIdx.y, tid = threadIdx.x;
    const float* xb = x + ((size_t)b * 256 * 4096 + (size_t)f * 64);
    for (int i = tid; i < 256 * 64; i += 256) {
        int ci = i >> 6, t = i & 63;
        s[t][ci] = __float2half_rn(xb[(size_t)ci * 4096 + t]);
    }
    __syncthreads();
    __half* dst = g_xT + ((size_t)(b * 64 + f)) * 64 * 256;
    for (int i = tid; i < 64 * 32; i += 256) {
        int t = i >> 5, c8 = (i & 31) * 8;
        *(uint4*)(dst + t * 256 + c8) = *(uint4*)&s[t][c8];
    }
}

// ---------------------------------------------------------------------------
// Kernel 4: conv via mma.sync m16n8k16.
// CTA=(b, coH 128co, 2 fo rows x 64 t). 8 warps: wco=wid>>1 (32co), wt=wid&1 (32t).
// 16 ci-chunks double-buffered. smem rows padded to 48B (conflict-free ldmatrix).
// B stored [t][ci] (= col-major for row.col mma) -> non-trans ldmatrix.
// ---------------------------------------------------------------------------
#define STG_A 55296          // 9 taps * 128 co * 48B
#define STG_B 12672          // 4 fi planes * 66 t-rows * 48B
#define B_BASE (2 * STG_A)
#define SMEM_CONV (2 * STG_A + 2 * STG_B)   // 135936

__global__ __launch_bounds__(256, 1) void conv_kernel(float* __restrict__ out) {
    extern __shared__ __align__(16) char smem[];
    const int tid = threadIdx.x, wid = tid >> 5, lane = tid & 31;
    const int b = blockIdx.z, coH = blockIdx.y, fo0 = blockIdx.x * 2;
    const int wco = wid >> 1, wt = wid & 1;
    const uint32_t sb = smem_u32(smem);

    // zero B region (halo rows/planes stay zero; cp.async only fills valid rows)
    for (int i = tid; i < 2 * STG_B / 4; i += 256)
        ((uint32_t*)(smem + B_BASE))[i] = 0u;
    __syncthreads();

    const __half* wbase = g_w16 + (((size_t)b * 2 + coH) * 16) * (9 * 128 * 16);

    auto load_stage = [&](int ch) {
        const int slot = ch & 1, ci0 = ch * 16;
        const __half* wsrc = wbase + (size_t)ch * (9 * 128 * 16);
        uint32_t ad = sb + slot * STG_A;
        for (int i = tid; i < 2304; i += 256) {
            int rc = i >> 1, q = i & 1;
            cp16(ad + rc * 48 + q * 16, wsrc + (size_t)i * 8);
        }
        uint32_t bd = sb + B_BASE + slot * STG_B;
        for (int i = tid; i < 512; i += 256) {
            int row = i >> 1, q = i & 1;
            int p = row >> 6, t = row & 63;
            int fi = fo0 - 1 + p;
            if ((unsigned)fi < 64u)
                cp16(bd + p * 3168 + (t + 1) * 48 + q * 16,
                     g_xT + (((size_t)(b * 64 + fi)) * 64 + t) * 256 + ci0 + q * 8);
        }
        asm volatile("cp.async.commit_group;" ::: "memory");
    };

    float acc[2][2][4][4];
#pragma unroll
    for (int r = 0; r < 2; ++r)
#pragma unroll
        for (int m = 0; m < 2; ++m)
#pragma unroll
            for (int n = 0; n < 4; ++n)
#pragma unroll
                for (int e = 0; e < 4; ++e) acc[r][m][n][e] = 0.f;

    load_stage(0);
    load_stage(1);

    const uint32_t aLane = (lane & 15) * 48 + (lane >> 4) * 16;
    const uint32_t bRow  = (lane & 7) + ((lane & 16) >> 1);    // +8 for upper n-half
    const uint32_t bCol  = (lane & 8) ? 16u : 0u;              // k high half

    for (int ch = 0; ch < 16; ++ch) {
        const int slot = ch & 1;
        if (ch < 14) asm volatile("cp.async.wait_group 1;" ::: "memory");
        else         asm volatile("cp.async.wait_group 0;" ::: "memory");
        __syncthreads();

        const uint32_t As = sb + slot * STG_A + (wco * 32) * 48 + aLane;
        const uint32_t Bs = sb + B_BASE + slot * STG_B + bRow * 48 + bCol;
#pragma unroll
        for (int kh = 0; kh < 3; ++kh) {
#pragma unroll
            for (int kw = 0; kw < 3; ++kw) {
                const int tap = kh * 3 + kw;
                uint32_t a[2][4];
                ldsm_x4(As + tap * 6144, a[0]);
                ldsm_x4(As + tap * 6144 + 16 * 48, a[1]);
#pragma unroll
                for (int r = 0; r < 2; ++r) {
                    const uint32_t Bp = Bs + (kh + r) * 3168 + kw * 48;
#pragma unroll
                    for (int nt = 0; nt < 2; ++nt) {
                        uint32_t bf[4];
                        ldsm_x4(Bp + (wt * 32 + nt * 16) * 48, bf);
#pragma unroll
                        for (int m = 0; m < 2; ++m) {
                            mma16816(acc[r][m][nt * 2],     a[m], bf);
                            mma16816(acc[r][m][nt * 2 + 1], a[m], bf + 2);
                        }
                    }
                }
            }
        }
        __syncthreads();
        if (ch + 2 < 16) load_stage(ch + 2);
    }

    // epilogue: direct float2 stores
    const int gRow = lane >> 2, col2 = (lane & 3) * 2;
#pragma unroll
    for (int r = 0; r < 2; ++r) {
        const int fo = fo0 + r;
#pragma unroll
        for (int m = 0; m < 2; ++m) {
            const int co = coH * 128 + wco * 32 + m * 16 + gRow;
#pragma unroll
            for (int n = 0; n < 4; ++n) {
                const int t = wt * 32 + (n >> 1) * 16 + (n & 1) * 8 + col2;
                size_t o0 = (((size_t)(b * 256 + co)) * 64 + fo) * 64 + t;
                *(float2*)&out[o0] = make_float2(acc[r][m][n][0], acc[r][m][n][1]);
                size_t o1 = o0 + 8 * 64 * 64;      // co + 8
                *(float2*)&out[o1] = make_float2(acc[r][m][n][2], acc[r][m][n][3]);
            }
        }
    }
}

// ---------------------------------------------------------------------------
extern "C" void kernel_launch(void* const* d_in, const int* in_sizes, int n_in,
                              void* d_out, int out_size) {
    const float* x  = (const float*)d_in[0];
    const float* g  = (const float*)d_in[1];
    const float* w  = (const float*)d_in[2];
    const float* dw = (const float*)d_in[3];
    const float* db = (const float*)d_in[4];
    float* out = (float*)d_out;

    attn_kernel<<<32, 128>>>(g, dw, db);
    agg16_kernel<<<1024, 256>>>(w);
    xT_kernel<<<dim3(64, 32), 256>>>(x);

    cudaFuncSetAttribute(conv_kernel,
                         cudaFuncAttributeMaxDynamicSharedMemorySize, SMEM_CONV);
    conv_kernel<<<dim3(32, 2, 32), 256, SMEM_CONV>>>(out);
}

// round 6
// speedup vs baseline: 9.3223x; 1.3688x over previous
#include <cuda_runtime.h>
#include <cuda_fp16.h>
#include <cstdint>

#define TEMP 30.0f

// ---------------- static device scratch ----------------
// aggregated fp16 weights: [b][coH(2)][chunk(16)][tap(9)][coL(128)][ci(16)]
__device__ __half g_w16[(size_t)32 * 2 * 16 * 9 * 128 * 16];
// transposed fp16 x: [b][f(64)][t(64)][ci(256)]
__device__ __half g_xT[(size_t)32 * 64 * 64 * 256];

// ---------------- helpers ----------------
__device__ __forceinline__ uint32_t smem_u32(const void* p) {
    uint32_t a;
    asm("{ .reg .u64 t; cvta.to.shared.u64 t, %1; cvt.u32.u64 %0, t; }" : "=r"(a) : "l"(p));
    return a;
}
__device__ __forceinline__ void cp16(uint32_t saddr, const void* g) {
    asm volatile("cp.async.cg.shared.global [%0], [%1], 16;" :: "r"(saddr), "l"(g));
}
__device__ __forceinline__ void ldsm_x4(uint32_t addr, uint32_t* r) {
    asm volatile("ldmatrix.sync.aligned.m8n8.x4.shared.b16 {%0,%1,%2,%3}, [%4];"
                 : "=r"(r[0]), "=r"(r[1]), "=r"(r[2]), "=r"(r[3]) : "r"(addr));
}
__device__ __forceinline__ void mma16816(float* d, const uint32_t* a,
                                         const uint32_t* b) {
    asm volatile(
        "mma.sync.aligned.m16n8k16.row.col.f32.f16.f16.f32 "
        "{%0,%1,%2,%3}, {%4,%5,%6,%7}, {%8,%9}, {%0,%1,%2,%3};"
        : "+f"(d[0]), "+f"(d[1]), "+f"(d[2]), "+f"(d[3])
        : "r"(a[0]), "r"(a[1]), "r"(a[2]), "r"(a[3]), "r"(b[0]), "r"(b[1]));
}

// ---------------------------------------------------------------------------
// Kernel 1: aggregate expert weights -> fp16 tiled layout (attention fused).
// Each block spans exactly one b (blockIdx.x>>5).
// ---------------------------------------------------------------------------
__global__ void agg16_kernel(const float* __restrict__ w,
                             const float* __restrict__ g,
                             const float* __restrict__ dw,
                             const float* __restrict__ db) {
    __shared__ float sp[4][4];
    __shared__ float s_att[4];
    const int b = blockIdx.x >> 5;
    const int tid = threadIdx.x;
    if (tid < 128) {
        int k = tid & 3, wrp = tid >> 5, lane = tid & 31;
        const float* gb = g + b * 256;
        float s = 0.f;
        for (int c = tid >> 2; c < 256; c += 32) s += gb[c] * dw[c * 4 + k];
        s += __shfl_xor_sync(~0u, s, 4);
        s += __shfl_xor_sync(~0u, s, 8);
        s += __shfl_xor_sync(~0u, s, 16);
        if (lane < 4) sp[wrp][k] = s;
    }
    __syncthreads();
    if (tid < 4) {
        int k = tid;
        float t = (sp[0][k] + sp[1][k] + sp[2][k] + sp[3][k] + db[k]) * (1.f / TEMP);
        float m = t;
        m = fmaxf(m, __shfl_xor_sync(0xF, m, 1));
        m = fmaxf(m, __shfl_xor_sync(0xF, m, 2));
        float e = expf(t - m);
        float su = e;
        su += __shfl_xor_sync(0xF, su, 1);
        su += __shfl_xor_sync(0xF, su, 2);
        s_att[k] = e / su;
    }
    __syncthreads();

    const int idx = blockIdx.x * 256 + tid;
    const int ci8 = idx & 31;
    const int co  = (idx >> 5) & 255;
    float acc[72];
#pragma unroll
    for (int e = 0; e < 72; ++e) acc[e] = 0.f;
#pragma unroll
    for (int k = 0; k < 4; ++k) {
        float a = s_att[k];
        const float4* wp =
            (const float4*)(w + (((size_t)k * 256 + co) * 256 + ci8 * 8) * 9);
#pragma unroll
        for (int q = 0; q < 18; ++q) {
            float4 f = wp[q];
            acc[q * 4 + 0] += a * f.x;
            acc[q * 4 + 1] += a * f.y;
            acc[q * 4 + 2] += a * f.z;
            acc[q * 4 + 3] += a * f.w;
        }
    }
    int coH = co >> 7, coL = co & 127, ch = ci8 >> 1, half8 = ci8 & 1;
#pragma unroll
    for (int kk = 0; kk < 9; ++kk) {
        __half2 h[4];
#pragma unroll
        for (int p = 0; p < 4; ++p)
            h[p] = __halves2half2(__float2half_rn(acc[(2 * p) * 9 + kk]),
                                  __float2half_rn(acc[(2 * p + 1) * 9 + kk]));
        __half* dst = g_w16 +
            (((((size_t)b * 2 + coH) * 16 + ch) * 9 + kk) * 128 + coL) * 16 + half8 * 8;
        *(uint4*)dst = *(uint4*)h;
    }
}

// ---------------------------------------------------------------------------
// Kernel 2: x -> fp16 transposed [b][f][t][ci]
// ---------------------------------------------------------------------------
__global__ void xT_kernel(const float* __restrict__ x) {
    __shared__ __half s[64][272];
    int f = blockIdx.x, b = blockIdx.y, tid = threadIdx.x;
    const float* xb = x + ((size_t)b * 256 * 4096 + (size_t)f * 64);
    for (int i = tid; i < 256 * 64; i += 256) {
        int ci = i >> 6, t = i & 63;
        s[t][ci] = __float2half_rn(xb[(size_t)ci * 4096 + t]);
    }
    __syncthreads();
    __half* dst = g_xT + ((size_t)(b * 64 + f)) * 64 * 256;
    for (int i = tid; i < 64 * 32; i += 256) {
        int t = i >> 5, c8 = (i & 31) * 8;
        *(uint4*)(dst + t * 256 + c8) = *(uint4*)&s[t][c8];
    }
}

// ---------------------------------------------------------------------------
// Kernel 3: conv via mma.sync m16n8k16.
// CTA = (b, coH 128co, 4 fo rows x 64 t). 8 warps: wco=wid&1 (64co), wfo=wid>>1.
// Warp tile 64co x 64t x 1fo. 16 ci-chunks, 3-stage cp.async pipeline.
// B stored [t][ci16] rows padded to 48B; halo rows stay zero.
// ---------------------------------------------------------------------------
#define STG_A 55296          // 9 taps * 128 co * 48B
#define STG_B 19008          // 6 fi planes * 66 t-rows * 48B
#define NSTG 3
#define B_BASE (NSTG * STG_A)
#define SMEM_CONV (NSTG * STG_A + NSTG * STG_B)   // 222912

__global__ __launch_bounds__(256, 1) void conv_kernel(float* __restrict__ out) {
    extern __shared__ __align__(16) char smem[];
    const int tid = threadIdx.x, wid = tid >> 5, lane = tid & 31;
    const int b = blockIdx.z, coH = blockIdx.y, fo0 = blockIdx.x * 4;
    const int wco = wid & 1, wfo = wid >> 1;
    const uint32_t sb = smem_u32(smem);

    // zero all B stages (halo rows/planes stay zero forever)
    for (int i = tid; i < NSTG * STG_B / 4; i += 256)
        ((uint32_t*)(smem + B_BASE))[i] = 0u;
    __syncthreads();

    const __half* wbase = g_w16 + (((size_t)b * 2 + coH) * 16) * (9 * 128 * 16);

    auto load_stage = [&](int ch) {
        const int slot = ch % NSTG, ci0 = ch * 16;
        const __half* wsrc = wbase + (size_t)ch * (9 * 128 * 16);
        uint32_t ad = sb + slot * STG_A;
        for (int i = tid; i < 2304; i += 256) {
            int rc = i >> 1, q = i & 1;
            cp16(ad + rc * 48 + q * 16, wsrc + (size_t)i * 8);
        }
        uint32_t bd = sb + B_BASE + slot * STG_B;
        for (int i = tid; i < 768; i += 256) {
            int row = i >> 1, q = i & 1;
            int p = row >> 6, t = row & 63;
            int fi = fo0 - 1 + p;
            if ((unsigned)fi < 64u)
                cp16(bd + p * 3168 + (t + 1) * 48 + q * 16,
                     g_xT + (((size_t)(b * 64 + fi)) * 64 + t) * 256 + ci0 + q * 8);
        }
        asm volatile("cp.async.commit_group;" ::: "memory");
    };

    float acc[4][8][4];
#pragma unroll
    for (int m = 0; m < 4; ++m)
#pragma unroll
        for (int n = 0; n < 8; ++n)
#pragma unroll
            for (int e = 0; e < 4; ++e) acc[m][n][e] = 0.f;

    load_stage(0);
    load_stage(1);
    load_stage(2);

    const uint32_t aLane = (lane & 15) * 48 + (lane >> 4) * 16;
    const uint32_t bLane = ((lane & 7) + ((lane & 16) >> 1)) * 48 +
                           ((lane & 8) ? 16u : 0u);

    for (int ch = 0; ch < 16; ++ch) {
        const int slot = ch % NSTG;
        if (ch <= 13)      asm volatile("cp.async.wait_group 2;" ::: "memory");
        else if (ch == 14) asm volatile("cp.async.wait_group 1;" ::: "memory");
        else               asm volatile("cp.async.wait_group 0;" ::: "memory");
        __syncthreads();

        const uint32_t As = sb + slot * STG_A + (wco * 64) * 48 + aLane;
        const uint32_t Bs = sb + B_BASE + slot * STG_B + (wfo * 3168) + bLane;
#pragma unroll
        for (int kh = 0; kh < 3; ++kh) {
#pragma unroll
            for (int kw = 0; kw < 3; ++kw) {
                const int tap = kh * 3 + kw;
                uint32_t a[4][4];
#pragma unroll
                for (int m = 0; m < 4; ++m)
                    ldsm_x4(As + tap * 6144 + m * 768, a[m]);
                uint32_t bf[4][4];
                const uint32_t Bp = Bs + kh * 3168 + kw * 48;
#pragma unroll
                for (int nt = 0; nt < 4; ++nt)
                    ldsm_x4(Bp + nt * 768, bf[nt]);
#pragma unroll
                for (int m = 0; m < 4; ++m)
#pragma unroll
                    for (int nt = 0; nt < 4; ++nt) {
                        mma16816(acc[m][nt * 2],     a[m], bf[nt]);
                        mma16816(acc[m][nt * 2 + 1], a[m], bf[nt] + 2);
                    }
            }
        }
        __syncthreads();
        if (ch + 3 < 16) load_stage(ch + 3);
    }

    // epilogue: direct float2 stores
    const int gRow = lane >> 2, col2 = (lane & 3) * 2;
    const int fo = fo0 + wfo;
#pragma unroll
    for (int m = 0; m < 4; ++m) {
        const int co = coH * 128 + wco * 64 + m * 16 + gRow;
#pragma unroll
        for (int nt = 0; nt < 4; ++nt)
#pragma unroll
            for (int j = 0; j < 2; ++j) {
                const int t = nt * 16 + j * 8 + col2;
                const float* d = acc[m][nt * 2 + j];
                size_t o0 = (((size_t)(b * 256 + co)) * 64 + fo) * 64 + t;
                *(float2*)&out[o0] = make_float2(d[0], d[1]);
                size_t o1 = o0 + 8 * 64 * 64;   // co + 8
                *(float2*)&out[o1] = make_float2(d[2], d[3]);
            }
    }
}

// ---------------------------------------------------------------------------
extern "C" void kernel_launch(void* const* d_in, const int* in_sizes, int n_in,
                              void* d_out, int out_size) {
    const float* x  = (const float*)d_in[0];
    const float* g  = (const float*)d_in[1];
    const float* w  = (const float*)d_in[2];
    const float* dw = (const float*)d_in[3];
    const float* db = (const float*)d_in[4];
    float* out = (float*)d_out;

    xT_kernel<<<dim3(64, 32), 256>>>(x);
    agg16_kernel<<<1024, 256>>>(w, g, dw, db);

    cudaFuncSetAttribute(conv_kernel,
                         cudaFuncAttributeMaxDynamicSharedMemorySize, SMEM_CONV);
    conv_kernel<<<dim3(16, 2, 32), 256, SMEM_CONV>>>(out);
}